// round 15
// baseline (speedup 1.0000x reference)
#include <cuda_runtime.h>
#include <cuda_bf16.h>
#include <cstdint>

#define B_SZ 1024
#define FIN  4096
#define NMEM 256
#define SQF  64
#define QKN  16384
typedef __nv_bfloat16 bf16;

// scratch
__device__ float g_tmp[B_SZ * QKN];                 // relu(xk) fp32
__device__ float g_part[128 * B_SZ * SQF];          // qsum partials per n-tile
__device__ float g_qsum[B_SZ * SQF];
__device__ float g_v2p[4 * NMEM * FIN];             // V2 split-K partials
__device__ bf16 g_savgh[B_SZ * NMEM], g_savgl[B_SZ * NMEM];
__device__ bf16 g_v2h[NMEM * FIN], g_v2l[NMEM * FIN];   // V2 = v @ Wl
__device__ bf16 g_vh[NMEM * FIN], g_vl[NMEM * FIN];
__device__ bf16 g_wlh[FIN * FIN], g_wll[FIN * FIN];
__device__ bf16 g_xh[B_SZ * FIN];

__device__ __forceinline__ uint32_t smem_u32(const void* p) {
    uint32_t a;
    asm("{ .reg .u64 t; cvta.to.shared.u64 t, %1; cvt.u32.u64 %0, t; }"
        : "=r"(a) : "l"(p));
    return a;
}
__device__ __forceinline__ void ldsm4(uint32_t* r, uint32_t a) {
    asm volatile("ldmatrix.sync.aligned.m8n8.x4.shared.b16 {%0,%1,%2,%3}, [%4];"
                 : "=r"(r[0]), "=r"(r[1]), "=r"(r[2]), "=r"(r[3]) : "r"(a));
}
__device__ __forceinline__ void ldsm4t(uint32_t* r, uint32_t a) {
    asm volatile("ldmatrix.sync.aligned.m8n8.x4.trans.shared.b16 {%0,%1,%2,%3}, [%4];"
                 : "=r"(r[0]), "=r"(r[1]), "=r"(r[2]), "=r"(r[3]) : "r"(a));
}
__device__ __forceinline__ void mma_bf16(float* d, const uint32_t* a, const uint32_t* b) {
    asm volatile(
        "mma.sync.aligned.m16n8k16.row.col.f32.bf16.bf16.f32 "
        "{%0,%1,%2,%3}, {%4,%5,%6,%7}, {%8,%9}, {%0,%1,%2,%3};"
        : "+f"(d[0]), "+f"(d[1]), "+f"(d[2]), "+f"(d[3])
        : "r"(a[0]), "r"(a[1]), "r"(a[2]), "r"(a[3]), "r"(b[0]), "r"(b[1]));
}
__device__ __forceinline__ void cpa16(uint32_t dst, const void* src) {
    asm volatile("cp.async.ca.shared.global [%0], [%1], 16;" :: "r"(dst), "l"(src));
}
__device__ __forceinline__ void cpa_commit() {
    asm volatile("cp.async.commit_group;" ::: "memory");
}
template<int N> __device__ __forceinline__ void cpa_wait() {
    asm volatile("cp.async.wait_group %0;" :: "n"(N) : "memory");
}
__device__ __forceinline__ void split2(float x, float y, uint32_t& hi, uint32_t& lo) {
    bf16 hx = __float2bfloat16(x);
    bf16 hy = __float2bfloat16(y);
    bf16 lx = __float2bfloat16(x - __bfloat162float(hx));
    bf16 ly = __float2bfloat16(y - __bfloat162float(hy));
    hi = (uint32_t)__bfloat16_as_ushort(hx) | ((uint32_t)__bfloat16_as_ushort(hy) << 16);
    lo = (uint32_t)__bfloat16_as_ushort(lx) | ((uint32_t)__bfloat16_as_ushort(ly) << 16);
}
__device__ __forceinline__ uint32_t pack_h(float x, float y) {
    uint32_t r;
    asm("cvt.rn.bf16x2.f32 %0, %1, %2;" : "=r"(r) : "f"(y), "f"(x));
    return r;
}

// fp32 -> bf16 hi/lo, 8 floats per iteration, 16B stores
__global__ void conv_kernel(const float4* __restrict__ in,
                            uint4* __restrict__ hi, uint4* __restrict__ lo, int n8)
{
    int i = blockIdx.x * blockDim.x + threadIdx.x;
    const int stride = gridDim.x * blockDim.x;
    for (; i < n8; i += stride) {
        float4 a = in[2 * i], b = in[2 * i + 1];
        uint32_t h0, l0, h1, l1, h2, l2, h3, l3;
        split2(a.x, a.y, h0, l0);
        split2(a.z, a.w, h1, l1);
        split2(b.x, b.y, h2, l2);
        split2(b.z, b.w, h3, l3);
        hi[i] = make_uint4(h0, h1, h2, h3);
        lo[i] = make_uint4(l0, l1, l2, l3);
    }
}
// fp32 -> bf16 (round only), 8 floats per iteration, 16B stores
__global__ void conv1_kernel(const float4* __restrict__ in,
                             uint4* __restrict__ hi, int n8)
{
    int i = blockIdx.x * blockDim.x + threadIdx.x;
    const int stride = gridDim.x * blockDim.x;
    for (; i < n8; i += stride) {
        float4 a = in[2 * i], b = in[2 * i + 1];
        hi[i] = make_uint4(pack_h(a.x, a.y), pack_h(a.z, a.w),
                           pack_h(b.x, b.y), pack_h(b.z, b.w));
    }
}

// ---------------------------------------------------------------------------
// Q/K GEMM with in-kernel fp32->bf16 weight conversion.
// A = xh (bf16) [1024,4096], W = fp32 [4096,16384]. CTA 128x128, BK=32.
// Stage (24KB): A-bf16 8K | B-fp32 16K; x3 stages + 8K bf16 staging = 80KB.
// EPI: 1 = fused qsum partials, 0 = relu+bias fp32 store.
// ---------------------------------------------------------------------------
#define QSTG 24576
#define QSTAGING 73728
#define QSM  81920

template<int EPI>
__global__ __launch_bounds__(256, 2)
void qkgemm(const bf16* __restrict__ Ah, const float* __restrict__ W,
            const float* __restrict__ bias, float* __restrict__ C,
            float* __restrict__ part)
{
    const int N = QKN, K = FIN;
    extern __shared__ uint8_t smem[];
    const uint32_t sb = smem_u32(smem);
    const int tid = threadIdx.x;
    const int lane = tid & 31, wid = tid >> 5;
    const int wm = wid & 1, wn = wid >> 1;
    const int bm0 = blockIdx.x * 128, bn0 = blockIdx.y * 128;

    // A loader: 2 thr/row, 32B each (bf16)
    const int arow = tid >> 1, ac = (tid & 1) * 32;
    const bf16* pAh = Ah + (size_t)(bm0 + arow) * K + ac / 2;
    const uint32_t aswz = (uint32_t)((arow & 3) << 4);
    const uint32_t ao = (uint32_t)(arow * 64 + ac);
    // B loader: fp32, 8 thr/row, 64B (16 floats) each
    const int brow = tid >> 3, bseg = tid & 7;
    const float* pW = W + (size_t)brow * N + bn0 + bseg * 16;
    const uint32_t fb = (uint32_t)(brow * 512 + bseg * 64);
    const uint32_t fsw = (uint32_t)((brow & 7) << 4);
    // staging (bf16) position: same mapping as the old bf16 B stage
    const uint32_t bo = (uint32_t)(brow * 256 + bseg * 32);
    const uint32_t bswz = (uint32_t)((brow & 7) << 4);

    const int NC = K >> 5;   // 128

    auto issue = [&](int c) {
        const uint32_t u = sb + (uint32_t)(c % 3) * QSTG;
        const bf16* sA = pAh + c * 32;
        const float* sW = pW + (size_t)c * 32 * N;
        cpa16(u + ((ao) ^ aswz), sA);
        cpa16(u + ((ao + 16) ^ aswz), sA + 8);
        #pragma unroll
        for (int i = 0; i < 4; i++)
            cpa16(u + 8192 + ((fb + 16 * i) ^ fsw), sW + 4 * i);
        cpa_commit();
    };

    float acc[16][4];
    #pragma unroll
    for (int i = 0; i < 16; i++)
        #pragma unroll
        for (int j = 0; j < 4; j++) acc[i][j] = 0.f;

    issue(0); issue(1); issue(2);

    for (int c = 0; c < NC; c++) {
        cpa_wait<2>();
        __syncthreads();   // stage c ready; staging free (prev ldsm done)
        const uint32_t soff = (uint32_t)(c % 3) * QSTG;
        // convert this thread's 16 fp32 weights -> bf16 staging
        {
            const uint8_t* fp = smem + soff + 8192;
            float4 v0 = *(const float4*)(fp + ((fb)      ^ fsw));
            float4 v1 = *(const float4*)(fp + ((fb + 16) ^ fsw));
            float4 v2 = *(const float4*)(fp + ((fb + 32) ^ fsw));
            float4 v3 = *(const float4*)(fp + ((fb + 48) ^ fsw));
            uint4 lo128 = make_uint4(pack_h(v0.x, v0.y), pack_h(v0.z, v0.w),
                                     pack_h(v1.x, v1.y), pack_h(v1.z, v1.w));
            uint4 hi128 = make_uint4(pack_h(v2.x, v2.y), pack_h(v2.z, v2.w),
                                     pack_h(v3.x, v3.y), pack_h(v3.z, v3.w));
            *(uint4*)(smem + QSTAGING + ((bo) ^ bswz)) = lo128;
            *(uint4*)(smem + QSTAGING + ((bo + 16) ^ bswz)) = hi128;
        }
        __syncthreads();   // staging ready
        const uint32_t u = sb + soff;
        const uint32_t ub = sb + QSTAGING;
        #pragma unroll
        for (int ks = 0; ks < 2; ks++) {
            uint32_t ah[4][4], bh[2][4];
            #pragma unroll
            for (int mi = 0; mi < 4; mi++) {
                int row = wm * 64 + mi * 16 + (lane & 15);
                uint32_t ad = (uint32_t)(row * 64 + ks * 32 + (lane >> 4) * 16);
                uint32_t sw = ad ^ ((uint32_t)(row & 3) << 4);
                ldsm4(ah[mi], u + sw);
            }
            #pragma unroll
            for (int j = 0; j < 2; j++) {
                int kk = ks * 16 + (lane & 15);
                int nn = wn * 32 + j * 16 + (lane >> 4) * 8;
                uint32_t bd = (uint32_t)(kk * 256 + nn * 2);
                uint32_t sw = bd ^ ((uint32_t)(kk & 7) << 4);
                ldsm4t(bh[j], ub + sw);
            }
            #pragma unroll
            for (int mi = 0; mi < 4; mi++)
                #pragma unroll
                for (int nj = 0; nj < 4; nj++)
                    mma_bf16(acc[mi * 4 + nj], ah[mi], &bh[nj >> 1][(nj & 1) * 2]);
        }
        __syncthreads();   // all warps done reading stage c before it is reused
        issue(c + 3 < NC ? c + 3 : NC - 1);
    }
    cpa_wait<0>();
    __syncthreads();

    if (EPI == 1) {
        float* qs = (float*)smem;   // 32KB reuse
        if (wn < 2) {
            #pragma unroll
            for (int mi = 0; mi < 4; mi++) {
                int r0l = wm * 64 + mi * 16 + (lane >> 2);
                #pragma unroll
                for (int nj = 0; nj < 4; nj++) {
                    int col = wn * 32 + nj * 8 + (lane & 3) * 2;
                    float* d = acc[mi * 4 + nj];
                    float b0 = bias[bn0 + col];
                    float b1 = bias[bn0 + col + 1];
                    qs[r0l * 64 + col]           = fmaxf(d[0] + b0, 0.f);
                    qs[r0l * 64 + col + 1]       = fmaxf(d[1] + b1, 0.f);
                    qs[(r0l + 8) * 64 + col]     = fmaxf(d[2] + b0, 0.f);
                    qs[(r0l + 8) * 64 + col + 1] = fmaxf(d[3] + b1, 0.f);
                }
            }
        }
        __syncthreads();
        if (wn >= 2) {
            #pragma unroll
            for (int mi = 0; mi < 4; mi++) {
                int r0l = wm * 64 + mi * 16 + (lane >> 2);
                #pragma unroll
                for (int nj = 0; nj < 4; nj++) {
                    int col = wn * 32 + nj * 8 + (lane & 3) * 2;
                    float* d = acc[mi * 4 + nj];
                    float b0 = bias[bn0 + col];
                    float b1 = bias[bn0 + col + 1];
                    qs[r0l * 64 + col - 64]           += fmaxf(d[0] + b0, 0.f);
                    qs[r0l * 64 + col - 63]           += fmaxf(d[1] + b1, 0.f);
                    qs[(r0l + 8) * 64 + col - 64]     += fmaxf(d[2] + b0, 0.f);
                    qs[(r0l + 8) * 64 + col - 63]     += fmaxf(d[3] + b1, 0.f);
                }
            }
        }
        __syncthreads();
        for (int i = tid; i < 8192; i += 256)
            part[(size_t)blockIdx.y * (B_SZ * SQF) + bm0 * 64 + i] = qs[i];
        return;
    }

    #pragma unroll
    for (int mi = 0; mi < 4; mi++) {
        const int r0 = bm0 + wm * 64 + mi * 16 + (lane >> 2);
        #pragma unroll
        for (int nj = 0; nj < 4; nj++) {
            const int col = bn0 + wn * 32 + nj * 8 + (lane & 3) * 2;
            float* d = acc[mi * 4 + nj];
            float2 bb = *(const float2*)&bias[col];
            float2 o0 = make_float2(fmaxf(d[0] + bb.x, 0.f), fmaxf(d[1] + bb.y, 0.f));
            float2 o1 = make_float2(fmaxf(d[2] + bb.x, 0.f), fmaxf(d[3] + bb.y, 0.f));
            *(float2*)&C[(size_t)r0 * N + col] = o0;
            *(float2*)&C[(size_t)(r0 + 8) * N + col] = o1;
        }
    }
}

// ---------------------------------------------------------------------------
// bf16 split-3 GEMM (V2 and final). CTA 128x128, BK=32, 3-stage cp.async.
// blockIdx.z = split-K slice.
// ---------------------------------------------------------------------------
#define STAGE_B 32768

template<bool BIAS, bool RES, bool OUTF32P>
__global__ __launch_bounds__(256)
void tgemm(const bf16* __restrict__ Ah, const bf16* __restrict__ Al,
           const bf16* __restrict__ Bh, const bf16* __restrict__ Bl,
           const float* __restrict__ bias, const float* __restrict__ res,
           float* __restrict__ C, int M, int N, int K, int lda)
{
    extern __shared__ uint8_t smem[];
    const uint32_t sb = smem_u32(smem);
    const int tid = threadIdx.x;
    const int lane = tid & 31, wid = tid >> 5;
    const int wm = wid & 1, wn = wid >> 1;
    const int bm0 = blockIdx.x * 128, bn0 = blockIdx.y * 128;

    const int kz = blockIdx.z;
    Ah += (size_t)kz * K;
    Al += (size_t)kz * K;
    Bh += (size_t)kz * K * N;
    Bl += (size_t)kz * K * N;
    if (OUTF32P) C += (size_t)kz * (size_t)M * N;

    const int arow = tid >> 1, ac = (tid & 1) * 32;
    const int brow = tid >> 3, bc = (tid & 7) * 32;
    const bf16* pAh = Ah + (size_t)(bm0 + arow) * lda + ac / 2;
    const bf16* pAl = Al + (size_t)(bm0 + arow) * lda + ac / 2;
    const bf16* pBh = Bh + (size_t)brow * N + bn0 + bc / 2;
    const bf16* pBl = Bl + (size_t)brow * N + bn0 + bc / 2;
    const uint32_t aswz = (uint32_t)((arow & 3) << 4);
    const uint32_t bswz = (uint32_t)((brow & 7) << 4);
    const uint32_t ao = (uint32_t)(arow * 64 + ac);
    const uint32_t bo = (uint32_t)(brow * 256 + bc);

    const int NC = K >> 5;

    auto issue = [&](int c) {
        const uint32_t u = sb + (uint32_t)(c % 3) * STAGE_B;
        const bf16* sAh = pAh + c * 32;
        const bf16* sAl = pAl + c * 32;
        const bf16* sBh = pBh + (size_t)c * 32 * N;
        const bf16* sBl = pBl + (size_t)c * 32 * N;
        cpa16(u + ((ao) ^ aswz), sAh);
        cpa16(u + ((ao + 16) ^ aswz), sAh + 8);
        cpa16(u + 8192 + ((ao) ^ aswz), sAl);
        cpa16(u + 8192 + ((ao + 16) ^ aswz), sAl + 8);
        cpa16(u + 16384 + ((bo) ^ bswz), sBh);
        cpa16(u + 16384 + ((bo + 16) ^ bswz), sBh + 8);
        cpa16(u + 24576 + ((bo) ^ bswz), sBl);
        cpa16(u + 24576 + ((bo + 16) ^ bswz), sBl + 8);
        cpa_commit();
    };

    float acc[16][4];
    #pragma unroll
    for (int i = 0; i < 16; i++)
        #pragma unroll
        for (int j = 0; j < 4; j++) acc[i][j] = 0.f;

    issue(0); issue(1); issue(2);

    for (int c = 0; c < NC; c++) {
        cpa_wait<2>();
        __syncthreads();
        const uint32_t u = sb + (uint32_t)(c % 3) * STAGE_B;
        #pragma unroll
        for (int ks = 0; ks < 2; ks++) {
            uint32_t ah[4][4], al[4][4], bh[2][4], bl[2][4];
            #pragma unroll
            for (int mi = 0; mi < 4; mi++) {
                int row = wm * 64 + mi * 16 + (lane & 15);
                uint32_t ad = (uint32_t)(row * 64 + ks * 32 + (lane >> 4) * 16);
                uint32_t sw = ad ^ ((uint32_t)(row & 3) << 4);
                ldsm4(ah[mi], u + sw);
                ldsm4(al[mi], u + 8192 + sw);
            }
            #pragma unroll
            for (int j = 0; j < 2; j++) {
                int kk = ks * 16 + (lane & 15);
                int nn = wn * 32 + j * 16 + (lane >> 4) * 8;
                uint32_t bd = (uint32_t)(kk * 256 + nn * 2);
                uint32_t sw = bd ^ ((uint32_t)(kk & 7) << 4);
                ldsm4t(bh[j], u + 16384 + sw);
                ldsm4t(bl[j], u + 24576 + sw);
            }
            #pragma unroll
            for (int mi = 0; mi < 4; mi++)
                #pragma unroll
                for (int nj = 0; nj < 4; nj++) {
                    const uint32_t* Bh2 = &bh[nj >> 1][(nj & 1) * 2];
                    const uint32_t* Bl2 = &bl[nj >> 1][(nj & 1) * 2];
                    float* d = acc[mi * 4 + nj];
                    mma_bf16(d, ah[mi], Bh2);
                    mma_bf16(d, ah[mi], Bl2);
                    mma_bf16(d, al[mi], Bh2);
                }
        }
        __syncthreads();
        issue(c + 3 < NC ? c + 3 : NC - 1);
    }
    cpa_wait<0>();
    __syncthreads();

    #pragma unroll
    for (int mi = 0; mi < 4; mi++) {
        const int r0 = bm0 + wm * 64 + mi * 16 + (lane >> 2);
        #pragma unroll
        for (int nj = 0; nj < 4; nj++) {
            const int col = bn0 + wn * 32 + nj * 8 + (lane & 3) * 2;
            float* d = acc[mi * 4 + nj];
            float2 o0 = make_float2(d[0], d[1]);
            float2 o1 = make_float2(d[2], d[3]);
            if (BIAS) {
                float2 bb = *(const float2*)&bias[col];
                o0.x += bb.x; o0.y += bb.y; o1.x += bb.x; o1.y += bb.y;
            }
            if (RES) {
                float2 s0 = *(const float2*)&res[(size_t)r0 * N + col];
                float2 s1 = *(const float2*)&res[(size_t)(r0 + 8) * N + col];
                o0.x += s0.x; o0.y += s0.y; o1.x += s1.x; o1.y += s1.y;
            }
            *(float2*)&C[(size_t)r0 * N + col] = o0;
            *(float2*)&C[(size_t)(r0 + 8) * N + col] = o1;
        }
    }
}

// qsum[b,s] = sum over 128 n-tiles of partials
__global__ void qsum_reduce()
{
    const int idx = blockIdx.x * 256 + threadIdx.x;   // < 65536
    float s = 0.f;
    #pragma unroll 16
    for (int nt = 0; nt < 128; nt++) s += g_part[(size_t)nt * (B_SZ * SQF) + idx];
    g_qsum[idx] = s;
}

// V2 partial reduce (+ bf16 hi/lo split). 2 elements per thread.
__global__ void v2_reduce()
{
    const int i = blockIdx.x * 256 + threadIdx.x;   // < NMEM*FIN/2
    const int e = 2 * i;
    float s0 = g_v2p[e]     + g_v2p[NMEM * FIN + e]
             + g_v2p[2 * NMEM * FIN + e] + g_v2p[3 * NMEM * FIN + e];
    float s1 = g_v2p[e + 1] + g_v2p[NMEM * FIN + e + 1]
             + g_v2p[2 * NMEM * FIN + e + 1] + g_v2p[3 * NMEM * FIN + e + 1];
    uint32_t h, l;
    split2(s0, s1, h, l);
    ((uint32_t*)g_v2h)[i] = h;
    ((uint32_t*)g_v2l)[i] = l;
}

// s_avg[b,n] = (1/2048) sum_s xk[b,n*64+s] * qsum[b,s]   -> bf16 hi/lo
__global__ void savg_kernel()
{
    const int b = blockIdx.x, t = threadIdx.x;
    const int lane = t & 31, w = t >> 5;
    __shared__ float q[64];
    if (t < 64) q[t] = g_qsum[b * SQF + t];
    __syncthreads();
    const float* base = g_tmp + (size_t)b * QKN;
    const float inv = 1.0f / 2048.0f;
    for (int n = w; n < NMEM; n += 8) {
        float sum = base[n * SQF + lane] * q[lane]
                  + base[n * SQF + 32 + lane] * q[32 + lane];
        #pragma unroll
        for (int off = 16; off; off >>= 1)
            sum += __shfl_xor_sync(0xffffffffu, sum, off);
        if (lane == 0) {
            float val = sum * inv;
            bf16 h = __float2bfloat16(val);
            bf16 l = __float2bfloat16(val - __bfloat162float(h));
            g_savgh[b * NMEM + n] = h;
            g_savgl[b * NMEM + n] = l;
        }
    }
}

extern "C" void kernel_launch(void* const* d_in, const int* in_sizes, int n_in,
                              void* d_out, int out_size)
{
    const float* x  = (const float*)d_in[0];
    const float* Wq = (const float*)d_in[1];
    const float* bq = (const float*)d_in[2];
    const float* Wk = (const float*)d_in[3];
    const float* bk = (const float*)d_in[4];
    const float* v  = (const float*)d_in[5];
    const float* Wl = (const float*)d_in[6];
    const float* bl = (const float*)d_in[7];
    float* out = (float*)d_out;

    float *tmp, *partp, *v2p;
    cudaGetSymbolAddress((void**)&tmp, g_tmp);
    cudaGetSymbolAddress((void**)&partp, g_part);
    cudaGetSymbolAddress((void**)&v2p, g_v2p);
    bf16 *wlh,*wll,*vh,*vl,*sh,*sl,*v2h,*v2l,*xh;
    cudaGetSymbolAddress((void**)&wlh, g_wlh); cudaGetSymbolAddress((void**)&wll, g_wll);
    cudaGetSymbolAddress((void**)&vh, g_vh);   cudaGetSymbolAddress((void**)&vl, g_vl);
    cudaGetSymbolAddress((void**)&sh, g_savgh);cudaGetSymbolAddress((void**)&sl, g_savgl);
    cudaGetSymbolAddress((void**)&v2h, g_v2h); cudaGetSymbolAddress((void**)&v2l, g_v2l);
    cudaGetSymbolAddress((void**)&xh, g_xh);

    const int SM = 3 * STAGE_B;
    cudaFuncSetAttribute(qkgemm<1>, cudaFuncAttributeMaxDynamicSharedMemorySize, QSM);
    cudaFuncSetAttribute(qkgemm<0>, cudaFuncAttributeMaxDynamicSharedMemorySize, QSM);
    cudaFuncSetAttribute(tgemm<false, false, true>,
                         cudaFuncAttributeMaxDynamicSharedMemorySize, SM);
    cudaFuncSetAttribute(tgemm<true, true, false>,
                         cudaFuncAttributeMaxDynamicSharedMemorySize, SM);

    // ---- single stream, graph-capturable, allocation-free ----

    // x conversion (only conversion left on the Q/K path)
    conv1_kernel<<<512, 256>>>((const float4*)x, (uint4*)xh, B_SZ * FIN / 8);

    // Q: GEMM with in-kernel Wq conversion + fused qsum partials
    {
        dim3 g(B_SZ / 128, QKN / 128);
        qkgemm<1><<<g, 256, QSM>>>(xh, Wq, bq, nullptr, partp);
    }
    qsum_reduce<<<256, 256>>>();

    // K: GEMM with in-kernel Wk conversion -> relu(xk) fp32
    {
        dim3 g(B_SZ / 128, QKN / 128);
        qkgemm<0><<<g, 256, QSM>>>(xh, Wk, bk, tmp, nullptr);
    }
    savg_kernel<<<B_SZ, 256>>>();

    // V2 = v @ Wl (split-3, split-K x4, fp32 partials)
    conv_kernel<<<2048, 256>>>((const float4*)Wl, (uint4*)wlh, (uint4*)wll,
                               FIN * FIN / 8);
    conv_kernel<<<256, 256>>>((const float4*)v, (uint4*)vh, (uint4*)vl,
                              NMEM * FIN / 8);
    {
        dim3 g(NMEM / 128, FIN / 128, 4);
        tgemm<false, false, true><<<g, 256, SM>>>(
            vh, vl, wlh, wll, nullptr, nullptr, v2p, NMEM, FIN, FIN / 4, FIN);
    }
    v2_reduce<<<NMEM * FIN / 512, 256>>>();

    // out = x + s_avg @ V2 + bl   (K = 256)
    {
        dim3 g(B_SZ / 128, FIN / 128);
        tgemm<true, true, false><<<g, 256, SM>>>(
            sh, sl, v2h, v2l, bl, x, out, B_SZ, FIN, NMEM, NMEM);
    }
}

// round 16
// speedup vs baseline: 1.5920x; 1.5920x over previous
#include <cuda_runtime.h>
#include <cuda_bf16.h>
#include <cstdint>

#define B_SZ 1024
#define FIN  4096
#define NMEM 256
#define SQF  64
#define QKN  16384
typedef __nv_bfloat16 bf16;

// scratch
__device__ float g_part[128 * B_SZ * SQF];          // qsum partials per n-tile
__device__ float g_qsum[B_SZ * SQF];
__device__ float g_v2p[4 * NMEM * FIN];             // V2 split-K partials
__device__ bf16 g_savgh[B_SZ * NMEM], g_savgl[B_SZ * NMEM];
__device__ bf16 g_v2h[NMEM * FIN], g_v2l[NMEM * FIN];   // V2 = v @ Wl
__device__ bf16 g_vh[NMEM * FIN], g_vl[NMEM * FIN];
__device__ bf16 g_wlh[FIN * FIN], g_wll[FIN * FIN];
__device__ bf16 g_xh[B_SZ * FIN];
__device__ bf16 g_wqh[(size_t)FIN * QKN];
__device__ bf16 g_wkh[(size_t)FIN * QKN];

__device__ __forceinline__ uint32_t smem_u32(const void* p) {
    uint32_t a;
    asm("{ .reg .u64 t; cvta.to.shared.u64 t, %1; cvt.u32.u64 %0, t; }"
        : "=r"(a) : "l"(p));
    return a;
}
__device__ __forceinline__ void ldsm4(uint32_t* r, uint32_t a) {
    asm volatile("ldmatrix.sync.aligned.m8n8.x4.shared.b16 {%0,%1,%2,%3}, [%4];"
                 : "=r"(r[0]), "=r"(r[1]), "=r"(r[2]), "=r"(r[3]) : "r"(a));
}
__device__ __forceinline__ void ldsm4t(uint32_t* r, uint32_t a) {
    asm volatile("ldmatrix.sync.aligned.m8n8.x4.trans.shared.b16 {%0,%1,%2,%3}, [%4];"
                 : "=r"(r[0]), "=r"(r[1]), "=r"(r[2]), "=r"(r[3]) : "r"(a));
}
__device__ __forceinline__ void mma_bf16(float* d, const uint32_t* a, const uint32_t* b) {
    asm volatile(
        "mma.sync.aligned.m16n8k16.row.col.f32.bf16.bf16.f32 "
        "{%0,%1,%2,%3}, {%4,%5,%6,%7}, {%8,%9}, {%0,%1,%2,%3};"
        : "+f"(d[0]), "+f"(d[1]), "+f"(d[2]), "+f"(d[3])
        : "r"(a[0]), "r"(a[1]), "r"(a[2]), "r"(a[3]), "r"(b[0]), "r"(b[1]));
}
__device__ __forceinline__ void cpa16(uint32_t dst, const void* src) {
    asm volatile("cp.async.ca.shared.global [%0], [%1], 16;" :: "r"(dst), "l"(src));
}
__device__ __forceinline__ void cpa_commit() {
    asm volatile("cp.async.commit_group;" ::: "memory");
}
template<int N> __device__ __forceinline__ void cpa_wait() {
    asm volatile("cp.async.wait_group %0;" :: "n"(N) : "memory");
}
__device__ __forceinline__ void split2(float x, float y, uint32_t& hi, uint32_t& lo) {
    bf16 hx = __float2bfloat16(x);
    bf16 hy = __float2bfloat16(y);
    bf16 lx = __float2bfloat16(x - __bfloat162float(hx));
    bf16 ly = __float2bfloat16(y - __bfloat162float(hy));
    hi = (uint32_t)__bfloat16_as_ushort(hx) | ((uint32_t)__bfloat16_as_ushort(hy) << 16);
    lo = (uint32_t)__bfloat16_as_ushort(lx) | ((uint32_t)__bfloat16_as_ushort(ly) << 16);
}
__device__ __forceinline__ uint32_t pack_h(float x, float y) {
    uint32_t r;
    asm("cvt.rn.bf16x2.f32 %0, %1, %2;" : "=r"(r) : "f"(y), "f"(x));
    return r;
}

// fp32 -> bf16 hi/lo, 8 floats per iteration, 16B stores
__global__ void conv_kernel(const float4* __restrict__ in,
                            uint4* __restrict__ hi, uint4* __restrict__ lo, int n8)
{
    int i = blockIdx.x * blockDim.x + threadIdx.x;
    const int stride = gridDim.x * blockDim.x;
    for (; i < n8; i += stride) {
        float4 a = in[2 * i], b = in[2 * i + 1];
        uint32_t h0, l0, h1, l1, h2, l2, h3, l3;
        split2(a.x, a.y, h0, l0);
        split2(a.z, a.w, h1, l1);
        split2(b.x, b.y, h2, l2);
        split2(b.z, b.w, h3, l3);
        hi[i] = make_uint4(h0, h1, h2, h3);
        lo[i] = make_uint4(l0, l1, l2, l3);
    }
}
// fp32 -> bf16 (round only), 8 floats per iteration, 16B stores
__global__ void conv1_kernel(const float4* __restrict__ in,
                             uint4* __restrict__ hi, int n8)
{
    int i = blockIdx.x * blockDim.x + threadIdx.x;
    const int stride = gridDim.x * blockDim.x;
    for (; i < n8; i += stride) {
        float4 a = in[2 * i], b = in[2 * i + 1];
        hi[i] = make_uint4(pack_h(a.x, a.y), pack_h(a.z, a.w),
                           pack_h(b.x, b.y), pack_h(b.z, b.w));
    }
}

// ---------------------------------------------------------------------------
// bf16 GEMM, TERMS=1 or 3. CTA 128x128, BK=32, 3-stage cp.async.
// EPI: 0 = store C (fp32 or bf16 hi/lo per OUTBF)
//      1 = fused qsum-partial epilogue (Q projection)
//      2 = fused s_avg epilogue (K projection; res = qsum, Ch/Cl = savg hi/lo)
// lda = A row stride. blockIdx.z = split-K slice.
// ---------------------------------------------------------------------------
#define STAGE_B 32768

template<int TERMS, int EPI, bool RELU, bool BIAS, bool RES, bool OUTBF>
__global__ __launch_bounds__(256)
void tgemm(const bf16* __restrict__ Ah, const bf16* __restrict__ Al,
           const bf16* __restrict__ Bh, const bf16* __restrict__ Bl,
           const float* __restrict__ bias, const float* __restrict__ res,
           float* __restrict__ C, bf16* __restrict__ Ch, bf16* __restrict__ Cl,
           float* __restrict__ part, int M, int N, int K, int lda)
{
    extern __shared__ uint8_t smem[];
    const uint32_t sb = smem_u32(smem);
    const int tid = threadIdx.x;
    const int lane = tid & 31, wid = tid >> 5;
    const int wm = wid & 1, wn = wid >> 1;
    const int bm0 = blockIdx.x * 128, bn0 = blockIdx.y * 128;

    const int kz = blockIdx.z;
    Ah += (size_t)kz * K;
    Bh += (size_t)kz * K * N;
    if (TERMS == 3) { Al += (size_t)kz * K; Bl += (size_t)kz * K * N; }
    if (!OUTBF && EPI == 0) C += (size_t)kz * (size_t)M * N;

    const int arow = tid >> 1, ac = (tid & 1) * 32;
    const int brow = tid >> 3, bc = (tid & 7) * 32;
    const bf16* pAh = Ah + (size_t)(bm0 + arow) * lda + ac / 2;
    const bf16* pAl = (TERMS == 3) ? Al + (size_t)(bm0 + arow) * lda + ac / 2 : nullptr;
    const bf16* pBh = Bh + (size_t)brow * N + bn0 + bc / 2;
    const bf16* pBl = (TERMS == 3) ? Bl + (size_t)brow * N + bn0 + bc / 2 : nullptr;
    const uint32_t aswz = (uint32_t)((arow & 3) << 4);
    const uint32_t bswz = (uint32_t)((brow & 7) << 4);
    const uint32_t ao = (uint32_t)(arow * 64 + ac);
    const uint32_t bo = (uint32_t)(brow * 256 + bc);

    const int NC = K >> 5;

    auto issue = [&](int c) {
        const uint32_t u = sb + (uint32_t)(c % 3) * STAGE_B;
        const bf16* sAh = pAh + c * 32;
        const bf16* sBh = pBh + (size_t)c * 32 * N;
        cpa16(u + ((ao) ^ aswz), sAh);
        cpa16(u + ((ao + 16) ^ aswz), sAh + 8);
        cpa16(u + 16384 + ((bo) ^ bswz), sBh);
        cpa16(u + 16384 + ((bo + 16) ^ bswz), sBh + 8);
        if (TERMS == 3) {
            const bf16* sAl = pAl + c * 32;
            const bf16* sBl = pBl + (size_t)c * 32 * N;
            cpa16(u + 8192 + ((ao) ^ aswz), sAl);
            cpa16(u + 8192 + ((ao + 16) ^ aswz), sAl + 8);
            cpa16(u + 24576 + ((bo) ^ bswz), sBl);
            cpa16(u + 24576 + ((bo + 16) ^ bswz), sBl + 8);
        }
        cpa_commit();
    };

    float acc[16][4];
    #pragma unroll
    for (int i = 0; i < 16; i++)
        #pragma unroll
        for (int j = 0; j < 4; j++) acc[i][j] = 0.f;

    issue(0); issue(1); issue(2);

    for (int c = 0; c < NC; c++) {
        cpa_wait<2>();
        __syncthreads();
        const uint32_t u = sb + (uint32_t)(c % 3) * STAGE_B;
        #pragma unroll
        for (int ks = 0; ks < 2; ks++) {
            uint32_t ah[4][4], al[4][4], bh[2][4], bl[2][4];
            #pragma unroll
            for (int mi = 0; mi < 4; mi++) {
                int row = wm * 64 + mi * 16 + (lane & 15);
                uint32_t ad = (uint32_t)(row * 64 + ks * 32 + (lane >> 4) * 16);
                uint32_t sw = ad ^ ((uint32_t)(row & 3) << 4);
                ldsm4(ah[mi], u + sw);
                if (TERMS == 3) ldsm4(al[mi], u + 8192 + sw);
            }
            #pragma unroll
            for (int j = 0; j < 2; j++) {
                int kk = ks * 16 + (lane & 15);
                int nn = wn * 32 + j * 16 + (lane >> 4) * 8;
                uint32_t bd = (uint32_t)(kk * 256 + nn * 2);
                uint32_t sw = bd ^ ((uint32_t)(kk & 7) << 4);
                ldsm4t(bh[j], u + 16384 + sw);
                if (TERMS == 3) ldsm4t(bl[j], u + 24576 + sw);
            }
            #pragma unroll
            for (int mi = 0; mi < 4; mi++)
                #pragma unroll
                for (int nj = 0; nj < 4; nj++) {
                    const uint32_t* Bh2 = &bh[nj >> 1][(nj & 1) * 2];
                    float* d = acc[mi * 4 + nj];
                    mma_bf16(d, ah[mi], Bh2);
                    if (TERMS == 3) {
                        const uint32_t* Bl2 = &bl[nj >> 1][(nj & 1) * 2];
                        mma_bf16(d, ah[mi], Bl2);
                        mma_bf16(d, al[mi], Bh2);
                    }
                }
        }
        __syncthreads();
        issue(c + 3 < NC ? c + 3 : NC - 1);
    }
    cpa_wait<0>();
    __syncthreads();

    if (EPI == 1) {
        // fused qsum partials
        float* qs = (float*)smem;   // 128*64 floats = 32KB
        if (wn < 2) {
            #pragma unroll
            for (int mi = 0; mi < 4; mi++) {
                int r0l = wm * 64 + mi * 16 + (lane >> 2);
                #pragma unroll
                for (int nj = 0; nj < 4; nj++) {
                    int col = wn * 32 + nj * 8 + (lane & 3) * 2;
                    float* d = acc[mi * 4 + nj];
                    float b0 = bias[bn0 + col];
                    float b1 = bias[bn0 + col + 1];
                    qs[r0l * 64 + col]           = fmaxf(d[0] + b0, 0.f);
                    qs[r0l * 64 + col + 1]       = fmaxf(d[1] + b1, 0.f);
                    qs[(r0l + 8) * 64 + col]     = fmaxf(d[2] + b0, 0.f);
                    qs[(r0l + 8) * 64 + col + 1] = fmaxf(d[3] + b1, 0.f);
                }
            }
        }
        __syncthreads();
        if (wn >= 2) {
            #pragma unroll
            for (int mi = 0; mi < 4; mi++) {
                int r0l = wm * 64 + mi * 16 + (lane >> 2);
                #pragma unroll
                for (int nj = 0; nj < 4; nj++) {
                    int col = wn * 32 + nj * 8 + (lane & 3) * 2;
                    float* d = acc[mi * 4 + nj];
                    float b0 = bias[bn0 + col];
                    float b1 = bias[bn0 + col + 1];
                    qs[r0l * 64 + col - 64]           += fmaxf(d[0] + b0, 0.f);
                    qs[r0l * 64 + col - 63]           += fmaxf(d[1] + b1, 0.f);
                    qs[(r0l + 8) * 64 + col - 64]     += fmaxf(d[2] + b0, 0.f);
                    qs[(r0l + 8) * 64 + col - 63]     += fmaxf(d[3] + b1, 0.f);
                }
            }
        }
        __syncthreads();
        for (int i = tid; i < 8192; i += 256)
            part[(size_t)blockIdx.y * (B_SZ * SQF) + bm0 * 64 + i] = qs[i];
        return;
    }

    if (EPI == 2) {
        // fused s_avg: this CTA's 128 cols = 2 full slots of 64 s-values.
        // qs [128 rows][128 cols] = 64KB, qsm [128 rows][64 s] = 32KB. Total 96KB.
        float* qs  = (float*)smem;
        float* qsm = (float*)(smem + 65536);
        #pragma unroll
        for (int mi = 0; mi < 4; mi++) {
            int r0l = wm * 64 + mi * 16 + (lane >> 2);
            #pragma unroll
            for (int nj = 0; nj < 4; nj++) {
                int col = wn * 32 + nj * 8 + (lane & 3) * 2;
                float* d = acc[mi * 4 + nj];
                float b0 = bias[bn0 + col];
                float b1 = bias[bn0 + col + 1];
                qs[r0l * 128 + col]           = fmaxf(d[0] + b0, 0.f);
                qs[r0l * 128 + col + 1]       = fmaxf(d[1] + b1, 0.f);
                qs[(r0l + 8) * 128 + col]     = fmaxf(d[2] + b0, 0.f);
                qs[(r0l + 8) * 128 + col + 1] = fmaxf(d[3] + b1, 0.f);
            }
        }
        for (int i = tid; i < 8192; i += 256)
            qsm[i] = res[bm0 * 64 + i];   // qsum tile for rows bm0..bm0+127
        __syncthreads();
        // 256 dots: pair p = (row, slot); warp w handles p = w*32 .. w*32+31
        const float inv = 1.0f / 2048.0f;
        #pragma unroll 4
        for (int i = 0; i < 32; i++) {
            int p = wid * 32 + i;
            int row = p >> 1, slot = p & 1;
            float sum = qs[row * 128 + slot * 64 + lane] * qsm[row * 64 + lane]
                      + qs[row * 128 + slot * 64 + 32 + lane] * qsm[row * 64 + 32 + lane];
            #pragma unroll
            for (int off = 16; off; off >>= 1)
                sum += __shfl_xor_sync(0xffffffffu, sum, off);
            if (lane == 0) {
                float val = sum * inv;
                bf16 h = __float2bfloat16(val);
                bf16 l = __float2bfloat16(val - __bfloat162float(h));
                int n = (bn0 >> 6) + slot;
                Ch[(size_t)(bm0 + row) * NMEM + n] = h;
                Cl[(size_t)(bm0 + row) * NMEM + n] = l;
            }
        }
        return;
    }

    #pragma unroll
    for (int mi = 0; mi < 4; mi++) {
        const int r0 = bm0 + wm * 64 + mi * 16 + (lane >> 2);
        #pragma unroll
        for (int nj = 0; nj < 4; nj++) {
            const int col = bn0 + wn * 32 + nj * 8 + (lane & 3) * 2;
            float* d = acc[mi * 4 + nj];
            if (OUTBF) {
                #pragma unroll
                for (int h = 0; h < 2; h++) {
                    const int rr = r0 + 8 * h;
                    uint32_t hi, lo;
                    split2(d[2 * h], d[2 * h + 1], hi, lo);
                    *(uint32_t*)&Ch[(size_t)rr * N + col] = hi;
                    *(uint32_t*)&Cl[(size_t)rr * N + col] = lo;
                }
            } else {
                float2 o0 = make_float2(d[0], d[1]);
                float2 o1 = make_float2(d[2], d[3]);
                if (BIAS) {
                    float2 bb = *(const float2*)&bias[col];
                    o0.x += bb.x; o0.y += bb.y; o1.x += bb.x; o1.y += bb.y;
                }
                if (RES) {
                    float2 s0 = *(const float2*)&res[(size_t)r0 * N + col];
                    float2 s1 = *(const float2*)&res[(size_t)(r0 + 8) * N + col];
                    o0.x += s0.x; o0.y += s0.y; o1.x += s1.x; o1.y += s1.y;
                }
                if (RELU) {
                    o0.x = fmaxf(o0.x, 0.f); o0.y = fmaxf(o0.y, 0.f);
                    o1.x = fmaxf(o1.x, 0.f); o1.y = fmaxf(o1.y, 0.f);
                }
                *(float2*)&C[(size_t)r0 * N + col] = o0;
                *(float2*)&C[(size_t)(r0 + 8) * N + col] = o1;
            }
        }
    }
}

// qsum[b,s] = sum over 128 n-tiles of partials
__global__ void qsum_reduce()
{
    const int idx = blockIdx.x * 256 + threadIdx.x;   // < 65536
    float s = 0.f;
    #pragma unroll 16
    for (int nt = 0; nt < 128; nt++) s += g_part[(size_t)nt * (B_SZ * SQF) + idx];
    g_qsum[idx] = s;
}

// V2 partial reduce (+ bf16 hi/lo split). 2 elements per thread.
__global__ void v2_reduce()
{
    const int i = blockIdx.x * 256 + threadIdx.x;   // < NMEM*FIN/2
    const int e = 2 * i;
    float s0 = g_v2p[e]     + g_v2p[NMEM * FIN + e]
             + g_v2p[2 * NMEM * FIN + e] + g_v2p[3 * NMEM * FIN + e];
    float s1 = g_v2p[e + 1] + g_v2p[NMEM * FIN + e + 1]
             + g_v2p[2 * NMEM * FIN + e + 1] + g_v2p[3 * NMEM * FIN + e + 1];
    uint32_t h, l;
    split2(s0, s1, h, l);
    ((uint32_t*)g_v2h)[i] = h;
    ((uint32_t*)g_v2l)[i] = l;
}

extern "C" void kernel_launch(void* const* d_in, const int* in_sizes, int n_in,
                              void* d_out, int out_size)
{
    const float* x  = (const float*)d_in[0];
    const float* Wq = (const float*)d_in[1];
    const float* bq = (const float*)d_in[2];
    const float* Wk = (const float*)d_in[3];
    const float* bk = (const float*)d_in[4];
    const float* v  = (const float*)d_in[5];
    const float* Wl = (const float*)d_in[6];
    const float* bl = (const float*)d_in[7];
    float* out = (float*)d_out;

    float *partp, *v2p, *qsump;
    cudaGetSymbolAddress((void**)&partp, g_part);
    cudaGetSymbolAddress((void**)&v2p, g_v2p);
    cudaGetSymbolAddress((void**)&qsump, g_qsum);
    bf16 *wlh,*wll,*vh,*vl,*sh,*sl,*v2h,*v2l,*xh,*wqh,*wkh;
    cudaGetSymbolAddress((void**)&wlh, g_wlh); cudaGetSymbolAddress((void**)&wll, g_wll);
    cudaGetSymbolAddress((void**)&vh, g_vh);   cudaGetSymbolAddress((void**)&vl, g_vl);
    cudaGetSymbolAddress((void**)&sh, g_savgh);cudaGetSymbolAddress((void**)&sl, g_savgl);
    cudaGetSymbolAddress((void**)&v2h, g_v2h); cudaGetSymbolAddress((void**)&v2l, g_v2l);
    cudaGetSymbolAddress((void**)&xh, g_xh);
    cudaGetSymbolAddress((void**)&wqh, g_wqh); cudaGetSymbolAddress((void**)&wkh, g_wkh);

    const int SM = 3 * STAGE_B;
    cudaFuncSetAttribute(tgemm<1, 1, true, true, false, false>,
                         cudaFuncAttributeMaxDynamicSharedMemorySize, SM);
    cudaFuncSetAttribute(tgemm<1, 2, true, true, false, false>,
                         cudaFuncAttributeMaxDynamicSharedMemorySize, SM);
    cudaFuncSetAttribute(tgemm<3, 0, false, false, false, false>,
                         cudaFuncAttributeMaxDynamicSharedMemorySize, SM);
    cudaFuncSetAttribute(tgemm<3, 0, false, true, true, false>,
                         cudaFuncAttributeMaxDynamicSharedMemorySize, SM);

    // ---- single stream, graph-capturable, allocation-free ----

    // x conversion
    conv1_kernel<<<512, 256>>>((const float4*)x, (uint4*)xh, B_SZ * FIN / 8);

    // Q branch: conv Wq, GEMM1 with fused qsum partials, reduce
    conv1_kernel<<<4096, 256>>>((const float4*)Wq, (uint4*)wqh, FIN * QKN / 8);
    {
        dim3 g(B_SZ / 128, QKN / 128);
        tgemm<1, 1, true, true, false, false><<<g, 256, SM>>>(
            xh, nullptr, wqh, nullptr, bq, nullptr, nullptr, nullptr, nullptr,
            partp, B_SZ, QKN, FIN, FIN);
    }
    qsum_reduce<<<256, 256>>>();

    // K branch: conv Wk, GEMM2 with fused s_avg epilogue (qsum is final)
    conv1_kernel<<<4096, 256>>>((const float4*)Wk, (uint4*)wkh, FIN * QKN / 8);
    {
        dim3 g(B_SZ / 128, QKN / 128);
        tgemm<1, 2, true, true, false, false><<<g, 256, SM>>>(
            xh, nullptr, wkh, nullptr, bk, qsump, nullptr, sh, sl,
            nullptr, B_SZ, QKN, FIN, FIN);
    }

    // V2 = v @ Wl (split-3, split-K x4, fp32 partials)
    conv_kernel<<<2048, 256>>>((const float4*)Wl, (uint4*)wlh, (uint4*)wll,
                               FIN * FIN / 8);
    conv_kernel<<<256, 256>>>((const float4*)v, (uint4*)vh, (uint4*)vl,
                              NMEM * FIN / 8);
    {
        dim3 g(NMEM / 128, FIN / 128, 4);
        tgemm<3, 0, false, false, false, false><<<g, 256, SM>>>(
            vh, vl, wlh, wll, nullptr, nullptr, v2p, nullptr, nullptr, nullptr,
            NMEM, FIN, FIN / 4, FIN);
    }
    v2_reduce<<<NMEM * FIN / 512, 256>>>();

    // out = x + s_avg @ V2 + bl   (K = 256)
    {
        dim3 g(B_SZ / 128, FIN / 128);
        tgemm<3, 0, false, true, true, false><<<g, 256, SM>>>(
            sh, sl, v2h, v2l, bl, x, out, nullptr, nullptr, nullptr,
            B_SZ, FIN, NMEM, NMEM);
    }
}

// round 17
// speedup vs baseline: 1.6266x; 1.0217x over previous
#include <cuda_runtime.h>
#include <cuda_bf16.h>
#include <cstdint>

#define B_SZ 1024
#define FIN  4096
#define NMEM 256
#define SQF  64
#define QKN  16384
typedef __nv_bfloat16 bf16;

// scratch
__device__ float g_part[128 * B_SZ * SQF];          // qsum partials per n-tile
__device__ float g_qsum[B_SZ * SQF];
__device__ float g_v2p[4 * NMEM * FIN];             // V2 split-K partials
__device__ bf16 g_savgh[B_SZ * NMEM], g_savgl[B_SZ * NMEM];
__device__ bf16 g_v2h[NMEM * FIN], g_v2l[NMEM * FIN];   // V2 = v @ Wl
__device__ bf16 g_vh[NMEM * FIN], g_vl[NMEM * FIN];
__device__ bf16 g_wlh[FIN * FIN], g_wll[FIN * FIN];
__device__ bf16 g_xh[B_SZ * FIN];
__device__ bf16 g_wqh[(size_t)FIN * QKN];
__device__ bf16 g_wkh[(size_t)FIN * QKN];

__device__ __forceinline__ uint32_t smem_u32(const void* p) {
    uint32_t a;
    asm("{ .reg .u64 t; cvta.to.shared.u64 t, %1; cvt.u32.u64 %0, t; }"
        : "=r"(a) : "l"(p));
    return a;
}
__device__ __forceinline__ void ldsm4(uint32_t* r, uint32_t a) {
    asm volatile("ldmatrix.sync.aligned.m8n8.x4.shared.b16 {%0,%1,%2,%3}, [%4];"
                 : "=r"(r[0]), "=r"(r[1]), "=r"(r[2]), "=r"(r[3]) : "r"(a));
}
__device__ __forceinline__ void ldsm4t(uint32_t* r, uint32_t a) {
    asm volatile("ldmatrix.sync.aligned.m8n8.x4.trans.shared.b16 {%0,%1,%2,%3}, [%4];"
                 : "=r"(r[0]), "=r"(r[1]), "=r"(r[2]), "=r"(r[3]) : "r"(a));
}
__device__ __forceinline__ void mma_bf16(float* d, const uint32_t* a, const uint32_t* b) {
    asm volatile(
        "mma.sync.aligned.m16n8k16.row.col.f32.bf16.bf16.f32 "
        "{%0,%1,%2,%3}, {%4,%5,%6,%7}, {%8,%9}, {%0,%1,%2,%3};"
        : "+f"(d[0]), "+f"(d[1]), "+f"(d[2]), "+f"(d[3])
        : "r"(a[0]), "r"(a[1]), "r"(a[2]), "r"(a[3]), "r"(b[0]), "r"(b[1]));
}
__device__ __forceinline__ void cpa16(uint32_t dst, const void* src) {
    asm volatile("cp.async.ca.shared.global [%0], [%1], 16;" :: "r"(dst), "l"(src));
}
__device__ __forceinline__ void cpa_commit() {
    asm volatile("cp.async.commit_group;" ::: "memory");
}
template<int N> __device__ __forceinline__ void cpa_wait() {
    asm volatile("cp.async.wait_group %0;" :: "n"(N) : "memory");
}
__device__ __forceinline__ void split2(float x, float y, uint32_t& hi, uint32_t& lo) {
    bf16 hx = __float2bfloat16(x);
    bf16 hy = __float2bfloat16(y);
    bf16 lx = __float2bfloat16(x - __bfloat162float(hx));
    bf16 ly = __float2bfloat16(y - __bfloat162float(hy));
    hi = (uint32_t)__bfloat16_as_ushort(hx) | ((uint32_t)__bfloat16_as_ushort(hy) << 16);
    lo = (uint32_t)__bfloat16_as_ushort(lx) | ((uint32_t)__bfloat16_as_ushort(ly) << 16);
}
__device__ __forceinline__ uint32_t pack_h(float x, float y) {
    uint32_t r;
    asm("cvt.rn.bf16x2.f32 %0, %1, %2;" : "=r"(r) : "f"(y), "f"(x));
    return r;
}

// fp32 -> bf16 hi/lo, 8 floats per iteration, 16B stores
__global__ void conv_kernel(const float4* __restrict__ in,
                            uint4* __restrict__ hi, uint4* __restrict__ lo, int n8)
{
    int i = blockIdx.x * blockDim.x + threadIdx.x;
    const int stride = gridDim.x * blockDim.x;
    for (; i < n8; i += stride) {
        float4 a = in[2 * i], b = in[2 * i + 1];
        uint32_t h0, l0, h1, l1, h2, l2, h3, l3;
        split2(a.x, a.y, h0, l0);
        split2(a.z, a.w, h1, l1);
        split2(b.x, b.y, h2, l2);
        split2(b.z, b.w, h3, l3);
        hi[i] = make_uint4(h0, h1, h2, h3);
        lo[i] = make_uint4(l0, l1, l2, l3);
    }
}
// fp32 -> bf16 (round only), 16 floats per iteration (4 LDG.128 up-front)
__global__ void conv1_kernel(const float4* __restrict__ in,
                             uint4* __restrict__ hi, int n16)
{
    int i = blockIdx.x * blockDim.x + threadIdx.x;
    const int stride = gridDim.x * blockDim.x;
    for (; i < n16; i += stride) {
        float4 a = in[4 * i], b = in[4 * i + 1];
        float4 c = in[4 * i + 2], d = in[4 * i + 3];
        hi[2 * i]     = make_uint4(pack_h(a.x, a.y), pack_h(a.z, a.w),
                                   pack_h(b.x, b.y), pack_h(b.z, b.w));
        hi[2 * i + 1] = make_uint4(pack_h(c.x, c.y), pack_h(c.z, c.w),
                                   pack_h(d.x, d.y), pack_h(d.z, d.w));
    }
}

// ---------------------------------------------------------------------------
// bf16 GEMM, TERMS=1 or 3.
//  TERMS=1: 4 stages x 16KB (A 8K | B 8K), ONE sync per chunk (issue-early).
//  TERMS=3: 3 stages x 32KB (Ah|Al|Bh|Bl), two syncs per chunk (proven).
// EPI: 0 = store C, 1 = fused qsum partials, 2 = fused s_avg.
// lda = A row stride. blockIdx.z = split-K slice.
// ---------------------------------------------------------------------------
#define STAGE_B 32768
#define STG1    16384

template<int TERMS, int EPI, bool RELU, bool BIAS, bool RES, bool OUTBF>
__global__ __launch_bounds__(256)
void tgemm(const bf16* __restrict__ Ah, const bf16* __restrict__ Al,
           const bf16* __restrict__ Bh, const bf16* __restrict__ Bl,
           const float* __restrict__ bias, const float* __restrict__ res,
           float* __restrict__ C, bf16* __restrict__ Ch, bf16* __restrict__ Cl,
           float* __restrict__ part, int M, int N, int K, int lda)
{
    extern __shared__ uint8_t smem[];
    const uint32_t sb = smem_u32(smem);
    const int tid = threadIdx.x;
    const int lane = tid & 31, wid = tid >> 5;
    const int wm = wid & 1, wn = wid >> 1;
    const int bm0 = blockIdx.x * 128, bn0 = blockIdx.y * 128;

    const int kz = blockIdx.z;
    Ah += (size_t)kz * K;
    Bh += (size_t)kz * K * N;
    if (TERMS == 3) { Al += (size_t)kz * K; Bl += (size_t)kz * K * N; }
    if (!OUTBF && EPI == 0) C += (size_t)kz * (size_t)M * N;

    const int arow = tid >> 1, ac = (tid & 1) * 32;
    const int brow = tid >> 3, bc = (tid & 7) * 32;
    const bf16* pAh = Ah + (size_t)(bm0 + arow) * lda + ac / 2;
    const bf16* pAl = (TERMS == 3) ? Al + (size_t)(bm0 + arow) * lda + ac / 2 : nullptr;
    const bf16* pBh = Bh + (size_t)brow * N + bn0 + bc / 2;
    const bf16* pBl = (TERMS == 3) ? Bl + (size_t)brow * N + bn0 + bc / 2 : nullptr;
    const uint32_t aswz = (uint32_t)((arow & 3) << 4);
    const uint32_t bswz = (uint32_t)((brow & 7) << 4);
    const uint32_t ao = (uint32_t)(arow * 64 + ac);
    const uint32_t bo = (uint32_t)(brow * 256 + bc);

    // per-variant layout constants
    const uint32_t BOFF = (TERMS == 3) ? 16384u : 8192u;   // B offset in stage

    const int NC = K >> 5;

    auto issue = [&](int c) {
        const uint32_t u = sb + (uint32_t)((TERMS == 3) ? (c % 3) * STAGE_B
                                                        : (c & 3) * STG1);
        const bf16* sAh = pAh + c * 32;
        const bf16* sBh = pBh + (size_t)c * 32 * N;
        cpa16(u + ((ao) ^ aswz), sAh);
        cpa16(u + ((ao + 16) ^ aswz), sAh + 8);
        cpa16(u + BOFF + ((bo) ^ bswz), sBh);
        cpa16(u + BOFF + ((bo + 16) ^ bswz), sBh + 8);
        if (TERMS == 3) {
            const bf16* sAl = pAl + c * 32;
            const bf16* sBl = pBl + (size_t)c * 32 * N;
            cpa16(u + 8192 + ((ao) ^ aswz), sAl);
            cpa16(u + 8192 + ((ao + 16) ^ aswz), sAl + 8);
            cpa16(u + 24576 + ((bo) ^ bswz), sBl);
            cpa16(u + 24576 + ((bo + 16) ^ bswz), sBl + 8);
        }
        cpa_commit();
    };

    float acc[16][4];
    #pragma unroll
    for (int i = 0; i < 16; i++)
        #pragma unroll
        for (int j = 0; j < 4; j++) acc[i][j] = 0.f;

    issue(0); issue(1); issue(2);

    for (int c = 0; c < NC; c++) {
        cpa_wait<2>();
        __syncthreads();
        // TERMS=1: 4 buffers -> issue early (targets buffer (c-1)&3, drained)
        if (TERMS == 1) issue(c + 3 < NC ? c + 3 : NC - 1);
        const uint32_t u = sb + (uint32_t)((TERMS == 3) ? (c % 3) * STAGE_B
                                                        : (c & 3) * STG1);
        #pragma unroll
        for (int ks = 0; ks < 2; ks++) {
            uint32_t ah[4][4], al[4][4], bh[2][4], bl[2][4];
            #pragma unroll
            for (int mi = 0; mi < 4; mi++) {
                int row = wm * 64 + mi * 16 + (lane & 15);
                uint32_t ad = (uint32_t)(row * 64 + ks * 32 + (lane >> 4) * 16);
                uint32_t sw = ad ^ ((uint32_t)(row & 3) << 4);
                ldsm4(ah[mi], u + sw);
                if (TERMS == 3) ldsm4(al[mi], u + 8192 + sw);
            }
            #pragma unroll
            for (int j = 0; j < 2; j++) {
                int kk = ks * 16 + (lane & 15);
                int nn = wn * 32 + j * 16 + (lane >> 4) * 8;
                uint32_t bd = (uint32_t)(kk * 256 + nn * 2);
                uint32_t sw = bd ^ ((uint32_t)(kk & 7) << 4);
                ldsm4t(bh[j], u + BOFF + sw);
                if (TERMS == 3) ldsm4t(bl[j], u + 24576 + sw);
            }
            #pragma unroll
            for (int mi = 0; mi < 4; mi++)
                #pragma unroll
                for (int nj = 0; nj < 4; nj++) {
                    const uint32_t* Bh2 = &bh[nj >> 1][(nj & 1) * 2];
                    float* d = acc[mi * 4 + nj];
                    mma_bf16(d, ah[mi], Bh2);
                    if (TERMS == 3) {
                        const uint32_t* Bl2 = &bl[nj >> 1][(nj & 1) * 2];
                        mma_bf16(d, ah[mi], Bl2);
                        mma_bf16(d, al[mi], Bh2);
                    }
                }
        }
        if (TERMS == 3) {
            __syncthreads();
            issue(c + 3 < NC ? c + 3 : NC - 1);
        }
    }
    cpa_wait<0>();
    __syncthreads();

    if (EPI == 1) {
        // fused qsum partials
        float* qs = (float*)smem;   // 128*64 floats = 32KB
        if (wn < 2) {
            #pragma unroll
            for (int mi = 0; mi < 4; mi++) {
                int r0l = wm * 64 + mi * 16 + (lane >> 2);
                #pragma unroll
                for (int nj = 0; nj < 4; nj++) {
                    int col = wn * 32 + nj * 8 + (lane & 3) * 2;
                    float* d = acc[mi * 4 + nj];
                    float b0 = bias[bn0 + col];
                    float b1 = bias[bn0 + col + 1];
                    qs[r0l * 64 + col]           = fmaxf(d[0] + b0, 0.f);
                    qs[r0l * 64 + col + 1]       = fmaxf(d[1] + b1, 0.f);
                    qs[(r0l + 8) * 64 + col]     = fmaxf(d[2] + b0, 0.f);
                    qs[(r0l + 8) * 64 + col + 1] = fmaxf(d[3] + b1, 0.f);
                }
            }
        }
        __syncthreads();
        if (wn >= 2) {
            #pragma unroll
            for (int mi = 0; mi < 4; mi++) {
                int r0l = wm * 64 + mi * 16 + (lane >> 2);
                #pragma unroll
                for (int nj = 0; nj < 4; nj++) {
                    int col = wn * 32 + nj * 8 + (lane & 3) * 2;
                    float* d = acc[mi * 4 + nj];
                    float b0 = bias[bn0 + col];
                    float b1 = bias[bn0 + col + 1];
                    qs[r0l * 64 + col - 64]           += fmaxf(d[0] + b0, 0.f);
                    qs[r0l * 64 + col - 63]           += fmaxf(d[1] + b1, 0.f);
                    qs[(r0l + 8) * 64 + col - 64]     += fmaxf(d[2] + b0, 0.f);
                    qs[(r0l + 8) * 64 + col - 63]     += fmaxf(d[3] + b1, 0.f);
                }
            }
        }
        __syncthreads();
        for (int i = tid; i < 8192; i += 256)
            part[(size_t)blockIdx.y * (B_SZ * SQF) + bm0 * 64 + i] = qs[i];
        return;
    }

    if (EPI == 2) {
        // fused s_avg: this CTA's 128 cols = 2 full slots of 64 s-values.
        float* qs  = (float*)smem;               // [128][128] = 64KB
        float* qsm = (float*)(smem + 65536);     // [128][64]  = 32KB
        #pragma unroll
        for (int mi = 0; mi < 4; mi++) {
            int r0l = wm * 64 + mi * 16 + (lane >> 2);
            #pragma unroll
            for (int nj = 0; nj < 4; nj++) {
                int col = wn * 32 + nj * 8 + (lane & 3) * 2;
                float* d = acc[mi * 4 + nj];
                float b0 = bias[bn0 + col];
                float b1 = bias[bn0 + col + 1];
                qs[r0l * 128 + col]           = fmaxf(d[0] + b0, 0.f);
                qs[r0l * 128 + col + 1]       = fmaxf(d[1] + b1, 0.f);
                qs[(r0l + 8) * 128 + col]     = fmaxf(d[2] + b0, 0.f);
                qs[(r0l + 8) * 128 + col + 1] = fmaxf(d[3] + b1, 0.f);
            }
        }
        for (int i = tid; i < 8192; i += 256)
            qsm[i] = res[bm0 * 64 + i];
        __syncthreads();
        const float inv = 1.0f / 2048.0f;
        #pragma unroll 4
        for (int i = 0; i < 32; i++) {
            int p = wid * 32 + i;
            int row = p >> 1, slot = p & 1;
            float sum = qs[row * 128 + slot * 64 + lane] * qsm[row * 64 + lane]
                      + qs[row * 128 + slot * 64 + 32 + lane] * qsm[row * 64 + 32 + lane];
            #pragma unroll
            for (int off = 16; off; off >>= 1)
                sum += __shfl_xor_sync(0xffffffffu, sum, off);
            if (lane == 0) {
                float val = sum * inv;
                bf16 h = __float2bfloat16(val);
                bf16 l = __float2bfloat16(val - __bfloat162float(h));
                int n = (bn0 >> 6) + slot;
                Ch[(size_t)(bm0 + row) * NMEM + n] = h;
                Cl[(size_t)(bm0 + row) * NMEM + n] = l;
            }
        }
        return;
    }

    #pragma unroll
    for (int mi = 0; mi < 4; mi++) {
        const int r0 = bm0 + wm * 64 + mi * 16 + (lane >> 2);
        #pragma unroll
        for (int nj = 0; nj < 4; nj++) {
            const int col = bn0 + wn * 32 + nj * 8 + (lane & 3) * 2;
            float* d = acc[mi * 4 + nj];
            if (OUTBF) {
                #pragma unroll
                for (int h = 0; h < 2; h++) {
                    const int rr = r0 + 8 * h;
                    uint32_t hi, lo;
                    split2(d[2 * h], d[2 * h + 1], hi, lo);
                    *(uint32_t*)&Ch[(size_t)rr * N + col] = hi;
                    *(uint32_t*)&Cl[(size_t)rr * N + col] = lo;
                }
            } else {
                float2 o0 = make_float2(d[0], d[1]);
                float2 o1 = make_float2(d[2], d[3]);
                if (BIAS) {
                    float2 bb = *(const float2*)&bias[col];
                    o0.x += bb.x; o0.y += bb.y; o1.x += bb.x; o1.y += bb.y;
                }
                if (RES) {
                    float2 s0 = *(const float2*)&res[(size_t)r0 * N + col];
                    float2 s1 = *(const float2*)&res[(size_t)(r0 + 8) * N + col];
                    o0.x += s0.x; o0.y += s0.y; o1.x += s1.x; o1.y += s1.y;
                }
                if (RELU) {
                    o0.x = fmaxf(o0.x, 0.f); o0.y = fmaxf(o0.y, 0.f);
                    o1.x = fmaxf(o1.x, 0.f); o1.y = fmaxf(o1.y, 0.f);
                }
                *(float2*)&C[(size_t)r0 * N + col] = o0;
                *(float2*)&C[(size_t)(r0 + 8) * N + col] = o1;
            }
        }
    }
}

// qsum[b,s] = sum over 128 n-tiles of partials
__global__ void qsum_reduce()
{
    const int idx = blockIdx.x * 256 + threadIdx.x;   // < 65536
    float s = 0.f;
    #pragma unroll 16
    for (int nt = 0; nt < 128; nt++) s += g_part[(size_t)nt * (B_SZ * SQF) + idx];
    g_qsum[idx] = s;
}

// V2 partial reduce (+ bf16 hi/lo split). 2 elements per thread.
__global__ void v2_reduce()
{
    const int i = blockIdx.x * 256 + threadIdx.x;   // < NMEM*FIN/2
    const int e = 2 * i;
    float s0 = g_v2p[e]     + g_v2p[NMEM * FIN + e]
             + g_v2p[2 * NMEM * FIN + e] + g_v2p[3 * NMEM * FIN + e];
    float s1 = g_v2p[e + 1] + g_v2p[NMEM * FIN + e + 1]
             + g_v2p[2 * NMEM * FIN + e + 1] + g_v2p[3 * NMEM * FIN + e + 1];
    uint32_t h, l;
    split2(s0, s1, h, l);
    ((uint32_t*)g_v2h)[i] = h;
    ((uint32_t*)g_v2l)[i] = l;
}

extern "C" void kernel_launch(void* const* d_in, const int* in_sizes, int n_in,
                              void* d_out, int out_size)
{
    const float* x  = (const float*)d_in[0];
    const float* Wq = (const float*)d_in[1];
    const float* bq = (const float*)d_in[2];
    const float* Wk = (const float*)d_in[3];
    const float* bk = (const float*)d_in[4];
    const float* v  = (const float*)d_in[5];
    const float* Wl = (const float*)d_in[6];
    const float* bl = (const float*)d_in[7];
    float* out = (float*)d_out;

    float *partp, *v2p, *qsump;
    cudaGetSymbolAddress((void**)&partp, g_part);
    cudaGetSymbolAddress((void**)&v2p, g_v2p);
    cudaGetSymbolAddress((void**)&qsump, g_qsum);
    bf16 *wlh,*wll,*vh,*vl,*sh,*sl,*v2h,*v2l,*xh,*wqh,*wkh;
    cudaGetSymbolAddress((void**)&wlh, g_wlh); cudaGetSymbolAddress((void**)&wll, g_wll);
    cudaGetSymbolAddress((void**)&vh, g_vh);   cudaGetSymbolAddress((void**)&vl, g_vl);
    cudaGetSymbolAddress((void**)&sh, g_savgh);cudaGetSymbolAddress((void**)&sl, g_savgl);
    cudaGetSymbolAddress((void**)&v2h, g_v2h); cudaGetSymbolAddress((void**)&v2l, g_v2l);
    cudaGetSymbolAddress((void**)&xh, g_xh);
    cudaGetSymbolAddress((void**)&wqh, g_wqh); cudaGetSymbolAddress((void**)&wkh, g_wkh);

    const int SM = 3 * STAGE_B;   // 96KB for all tgemm variants
    cudaFuncSetAttribute(tgemm<1, 1, true, true, false, false>,
                         cudaFuncAttributeMaxDynamicSharedMemorySize, SM);
    cudaFuncSetAttribute(tgemm<1, 2, true, true, false, false>,
                         cudaFuncAttributeMaxDynamicSharedMemorySize, SM);
    cudaFuncSetAttribute(tgemm<3, 0, false, false, false, false>,
                         cudaFuncAttributeMaxDynamicSharedMemorySize, SM);
    cudaFuncSetAttribute(tgemm<3, 0, false, true, true, false>,
                         cudaFuncAttributeMaxDynamicSharedMemorySize, SM);

    // ---- single stream, graph-capturable, allocation-free ----

    // x conversion
    conv1_kernel<<<512, 256>>>((const float4*)x, (uint4*)xh, B_SZ * FIN / 16);

    // Q branch: conv Wq, GEMM1 with fused qsum partials, reduce
    conv1_kernel<<<4096, 256>>>((const float4*)Wq, (uint4*)wqh, FIN * QKN / 16);
    {
        dim3 g(B_SZ / 128, QKN / 128);
        tgemm<1, 1, true, true, false, false><<<g, 256, SM>>>(
            xh, nullptr, wqh, nullptr, bq, nullptr, nullptr, nullptr, nullptr,
            partp, B_SZ, QKN, FIN, FIN);
    }
    qsum_reduce<<<256, 256>>>();

    // K branch: conv Wk, GEMM2 with fused s_avg epilogue (qsum is final)
    conv1_kernel<<<4096, 256>>>((const float4*)Wk, (uint4*)wkh, FIN * QKN / 16);
    {
        dim3 g(B_SZ / 128, QKN / 128);
        tgemm<1, 2, true, true, false, false><<<g, 256, SM>>>(
            xh, nullptr, wkh, nullptr, bk, qsump, nullptr, sh, sl,
            nullptr, B_SZ, QKN, FIN, FIN);
    }

    // V2 = v @ Wl (split-3, split-K x4, fp32 partials)
    conv_kernel<<<2048, 256>>>((const float4*)Wl, (uint4*)wlh, (uint4*)wll,
                               FIN * FIN / 8);
    conv_kernel<<<256, 256>>>((const float4*)v, (uint4*)vh, (uint4*)vl,
                              NMEM * FIN / 8);
    {
        dim3 g(NMEM / 128, FIN / 128, 4);
        tgemm<3, 0, false, false, false, false><<<g, 256, SM>>>(
            vh, vl, wlh, wll, nullptr, nullptr, v2p, nullptr, nullptr, nullptr,
            NMEM, FIN, FIN / 4, FIN);
    }
    v2_reduce<<<NMEM * FIN / 512, 256>>>();

    // out = x + s_avg @ V2 + bl   (K = 256)
    {
        dim3 g(B_SZ / 128, FIN / 128);
        tgemm<3, 0, false, true, true, false><<<g, 256, SM>>>(
            sh, sl, v2h, v2l, bl, x, out, nullptr, nullptr, nullptr,
            B_SZ, FIN, NMEM, NMEM);
    }
}